// round 1
// baseline (speedup 1.0000x reference)
#include <cuda_runtime.h>

#define NB 512      // number of segments / batch
#define C_IN 32
#define F1 64
#define F2 128
#define BN_EPS 1e-5f

// ---- scratch (no allocations allowed) ----
__device__ int   g_off[NB + 1];          // exclusive segment offsets
__device__ float g_mean[NB * C_IN];      // per-segment means [512,32]
__device__ float g_h[NB * F1];           // fc1 pre-BN activations [512,64]
__device__ float g_mu1[F1], g_inv1[F1];  // BN1 stats
__device__ float g_mu2[F2], g_inv2[F2];  // BN2 stats

// ---------------------------------------------------------------------------
// K1: inclusive scan of lengths -> g_off[0..512]
// ---------------------------------------------------------------------------
__global__ void k_scan(const int* __restrict__ len) {
    __shared__ int s[NB];
    int t = threadIdx.x;
    s[t] = len[t];
    __syncthreads();
    #pragma unroll
    for (int d = 1; d < NB; d <<= 1) {
        int v = (t >= d) ? s[t - d] : 0;
        __syncthreads();
        s[t] += v;
        __syncthreads();
    }
    if (t == 0) g_off[0] = 0;
    g_off[t + 1] = s[t];
}

// ---------------------------------------------------------------------------
// K2: per-segment channel means. One block per segment, float4 streaming.
// Row = 32 floats = 8 float4. Segment start s*8 is 0 mod 8, and stride 256 is
// 0 mod 8, so thread t always touches channel-quad (t & 7). Deterministic
// tree reduction preserving residue classes mod 8.
// ---------------------------------------------------------------------------
__global__ void k_segmean(const float4* __restrict__ x) {
    int b = blockIdx.x;
    int s = g_off[b];
    int e = g_off[b + 1];
    int js = s * 8;
    int je = e * 8;

    float4 acc = make_float4(0.f, 0.f, 0.f, 0.f);
    #pragma unroll 4
    for (int j = js + threadIdx.x; j < je; j += 256) {
        float4 v = x[j];
        acc.x += v.x; acc.y += v.y; acc.z += v.z; acc.w += v.w;
    }

    __shared__ float4 red[256];
    red[threadIdx.x] = acc;
    __syncthreads();
    #pragma unroll
    for (int step = 128; step >= 8; step >>= 1) {
        if (threadIdx.x < step) {
            float4 o = red[threadIdx.x + step];
            red[threadIdx.x].x += o.x;
            red[threadIdx.x].y += o.y;
            red[threadIdx.x].z += o.z;
            red[threadIdx.x].w += o.w;
        }
        __syncthreads();
    }
    if (threadIdx.x < 8) {
        float inv_len = 1.0f / (float)(e - s);
        float4 m = red[threadIdx.x];
        float* dst = &g_mean[b * C_IN + threadIdx.x * 4];
        dst[0] = m.x * inv_len;
        dst[1] = m.y * inv_len;
        dst[2] = m.z * inv_len;
        dst[3] = m.w * inv_len;
    }
}

// ---------------------------------------------------------------------------
// K3: h = mean @ W1 + b1   (one thread per output element, 512*64 threads)
// ---------------------------------------------------------------------------
__global__ void k_fc1(const float* __restrict__ W1, const float* __restrict__ b1) {
    int idx = blockIdx.x * blockDim.x + threadIdx.x;
    if (idx >= NB * F1) return;
    int r = idx >> 6;
    int c = idx & (F1 - 1);
    float acc = b1[c];
    #pragma unroll
    for (int k = 0; k < C_IN; k++)
        acc = fmaf(g_mean[r * C_IN + k], W1[k * F1 + c], acc);
    g_h[idx] = acc;
}

// ---------------------------------------------------------------------------
// K4: BN1 column stats over 512 rows of g_h (single block, 512 threads)
// ---------------------------------------------------------------------------
__global__ void k_stat1() {
    __shared__ float ps[8][F1];
    __shared__ float pq[8][F1];
    int t = threadIdx.x;
    int c = t & (F1 - 1);
    int ch = t >> 6;                 // 8 chunks of 64 rows
    float s = 0.f, q = 0.f;
    for (int r = ch * 64; r < ch * 64 + 64; r++) {
        float v = g_h[r * F1 + c];
        s += v;
        q += v * v;
    }
    ps[ch][c] = s;
    pq[ch][c] = q;
    __syncthreads();
    if (t < F1) {
        float S = 0.f, Q = 0.f;
        #pragma unroll
        for (int i = 0; i < 8; i++) { S += ps[i][t]; Q += pq[i][t]; }
        float mu  = S * (1.0f / (float)NB);
        float var = Q * (1.0f / (float)NB) - mu * mu;
        g_mu1[t]  = mu;
        g_inv1[t] = rsqrtf(var + BN_EPS);
    }
}

// ---------------------------------------------------------------------------
// K5: out_pre = relu(BN1(h)) @ W2 + b2  (one thread per output element)
// BN1 recomputed per column: trivial extra FLOPs, keeps everything fused.
// ---------------------------------------------------------------------------
__global__ void k_fc2(const float* __restrict__ g1, const float* __restrict__ beta1,
                      const float* __restrict__ W2, const float* __restrict__ b2,
                      float* __restrict__ out) {
    int idx = blockIdx.x * blockDim.x + threadIdx.x;
    if (idx >= NB * F2) return;
    int r = idx >> 7;
    int c = idx & (F2 - 1);
    float acc = b2[c];
    #pragma unroll
    for (int k = 0; k < F1; k++) {
        float a = g1[k] * (g_h[r * F1 + k] - g_mu1[k]) * g_inv1[k] + beta1[k];
        a = fmaxf(a, 0.f);
        acc = fmaf(a, W2[k * F2 + c], acc);
    }
    out[idx] = acc;
}

// ---------------------------------------------------------------------------
// K6: BN2 column stats over 512 rows of out (single block, 512 threads)
// ---------------------------------------------------------------------------
__global__ void k_stat2(const float* __restrict__ out) {
    __shared__ float ps[4][F2];
    __shared__ float pq[4][F2];
    int t = threadIdx.x;
    int c = t & (F2 - 1);
    int ch = t >> 7;                 // 4 chunks of 128 rows
    float s = 0.f, q = 0.f;
    for (int r = ch * 128; r < ch * 128 + 128; r++) {
        float v = out[r * F2 + c];
        s += v;
        q += v * v;
    }
    ps[ch][c] = s;
    pq[ch][c] = q;
    __syncthreads();
    if (t < F2) {
        float S = 0.f, Q = 0.f;
        #pragma unroll
        for (int i = 0; i < 4; i++) { S += ps[i][t]; Q += pq[i][t]; }
        float mu  = S * (1.0f / (float)NB);
        float var = Q * (1.0f / (float)NB) - mu * mu;
        g_mu2[t]  = mu;
        g_inv2[t] = rsqrtf(var + BN_EPS);
    }
}

// ---------------------------------------------------------------------------
// K7: apply BN2 in place
// ---------------------------------------------------------------------------
__global__ void k_bn2(const float* __restrict__ g2, const float* __restrict__ beta2,
                      float* __restrict__ out) {
    int idx = blockIdx.x * blockDim.x + threadIdx.x;
    if (idx >= NB * F2) return;
    int c = idx & (F2 - 1);
    out[idx] = g2[c] * (out[idx] - g_mu2[c]) * g_inv2[c] + beta2[c];
}

// ---------------------------------------------------------------------------
extern "C" void kernel_launch(void* const* d_in, const int* in_sizes, int n_in,
                              void* d_out, int out_size) {
    const float* x     = (const float*)d_in[0];
    const int*   len   = (const int*)  d_in[1];
    const float* W1    = (const float*)d_in[2];
    const float* b1    = (const float*)d_in[3];
    const float* g1    = (const float*)d_in[4];
    const float* beta1 = (const float*)d_in[5];
    const float* W2    = (const float*)d_in[6];
    const float* b2    = (const float*)d_in[7];
    const float* g2    = (const float*)d_in[8];
    const float* beta2 = (const float*)d_in[9];
    float* out = (float*)d_out;

    k_scan<<<1, NB>>>(len);
    k_segmean<<<NB, 256>>>((const float4*)x);
    k_fc1<<<(NB * F1 + 255) / 256, 256>>>(W1, b1);
    k_stat1<<<1, 512>>>();
    k_fc2<<<(NB * F2 + 255) / 256, 256>>>(g1, beta1, W2, b2, out);
    k_stat2<<<1, 512>>>(out);
    k_bn2<<<(NB * F2 + 255) / 256, 256>>>(g2, beta2, out);
}

// round 2
// speedup vs baseline: 1.0195x; 1.0195x over previous
#include <cuda_runtime.h>

#define NB 512      // number of segments / batch
#define C_IN 32
#define F1 64
#define F2 128
#define BN_EPS 1e-5f
#define TB 64       // tail grid (co-resident on 148 SMs -> spin barrier is safe)
#define TT 256      // tail block size

// ---- scratch (no allocations allowed) ----
__device__ int   g_off[NB + 1];
__device__ float g_mean[NB * C_IN];
__device__ float g_h[NB * F1];
__device__ __align__(16) float g_s1[F1];
__device__ __align__(16) float g_o1[F1];
__device__ __align__(16) float g_s2[F2];
__device__ __align__(16) float g_o2[F2];
__device__ unsigned g_barcnt;

// ---------------------------------------------------------------------------
// K1: inclusive scan of lengths -> g_off ; also resets the grid barrier
// counter for this launch (stream order guarantees prior tail finished).
// ---------------------------------------------------------------------------
__global__ void k_scan(const int* __restrict__ len) {
    __shared__ int s[NB];
    int t = threadIdx.x;
    if (t == 0) g_barcnt = 0;
    s[t] = len[t];
    __syncthreads();
    #pragma unroll
    for (int d = 1; d < NB; d <<= 1) {
        int v = (t >= d) ? s[t - d] : 0;
        __syncthreads();
        s[t] += v;
        __syncthreads();
    }
    if (t == 0) g_off[0] = 0;
    g_off[t + 1] = s[t];
}

// ---------------------------------------------------------------------------
// K2: per-segment channel means. One block per segment, streaming float4.
// All 512 blocks co-resident -> aggregate HBM-bandwidth bound.
// ---------------------------------------------------------------------------
__global__ void __launch_bounds__(256) k_segmean(const float4* __restrict__ x) {
    int b = blockIdx.x;
    int s = g_off[b];
    int e = g_off[b + 1];
    int js = s * 8;
    int je = e * 8;

    float4 a0 = make_float4(0.f, 0.f, 0.f, 0.f);
    float4 a1 = make_float4(0.f, 0.f, 0.f, 0.f);
    int j = js + threadIdx.x;
    // stride-512 dual-accumulator main loop (channel-quad class j&7 invariant:
    // js = s*8 is 0 mod 8 and strides are 0 mod 8)
    for (; j + 256 < je; j += 512) {
        float4 v0 = __ldcs(&x[j]);
        float4 v1 = __ldcs(&x[j + 256]);
        a0.x += v0.x; a0.y += v0.y; a0.z += v0.z; a0.w += v0.w;
        a1.x += v1.x; a1.y += v1.y; a1.z += v1.z; a1.w += v1.w;
    }
    if (j < je) {
        float4 v0 = __ldcs(&x[j]);
        a0.x += v0.x; a0.y += v0.y; a0.z += v0.z; a0.w += v0.w;
    }
    a0.x += a1.x; a0.y += a1.y; a0.z += a1.z; a0.w += a1.w;

    __shared__ float4 red[256];
    red[threadIdx.x] = a0;
    __syncthreads();
    #pragma unroll
    for (int step = 128; step >= 8; step >>= 1) {
        if (threadIdx.x < step) {
            float4 o = red[threadIdx.x + step];
            red[threadIdx.x].x += o.x;
            red[threadIdx.x].y += o.y;
            red[threadIdx.x].z += o.z;
            red[threadIdx.x].w += o.w;
        }
        __syncthreads();
    }
    if (threadIdx.x < 8) {
        float inv_len = 1.0f / (float)(e - s);
        float4 m = red[threadIdx.x];
        float* dst = &g_mean[b * C_IN + threadIdx.x * 4];
        dst[0] = m.x * inv_len;
        dst[1] = m.y * inv_len;
        dst[2] = m.z * inv_len;
        dst[3] = m.w * inv_len;
    }
}

// ---------------------------------------------------------------------------
// software grid barrier (TB blocks, all co-resident)
// ---------------------------------------------------------------------------
__device__ __forceinline__ void grid_bar(unsigned target) {
    __syncthreads();
    if (threadIdx.x == 0) {
        __threadfence();
        atomicAdd(&g_barcnt, 1u);
        while (*((volatile unsigned*)&g_barcnt) < target) { }
        __threadfence();
    }
    __syncthreads();
}

// ---------------------------------------------------------------------------
// K3: fused tail: fc1 -> BN1 stats -> relu/BN1 + fc2 -> BN2 stats -> BN2 apply
// ---------------------------------------------------------------------------
__global__ void __launch_bounds__(TT) k_tail(
    const float* __restrict__ W1, const float* __restrict__ b1,
    const float* __restrict__ g1, const float* __restrict__ be1,
    const float* __restrict__ W2, const float* __restrict__ b2,
    const float* __restrict__ g2, const float* __restrict__ be2,
    float* __restrict__ out)
{
    __shared__ float sW2[F1 * F2];   // 32 KiB
    __shared__ float sred[2 * TT];
    __shared__ float ss1[F1], so1[F1];

    int tid = threadIdx.x;
    int b   = blockIdx.x;
    int gt  = b * TT + tid;          // 0..16383

    // ---- Phase 1: g_h = mean @ W1 + b1 (2 outputs / thread) ----
    #pragma unroll
    for (int i = 0; i < 2; i++) {
        int idx = gt + i * (TB * TT);
        int r = idx >> 6;
        int c = idx & (F1 - 1);
        float acc = b1[c];
        #pragma unroll
        for (int k = 0; k < C_IN; k++)
            acc = fmaf(g_mean[r * C_IN + k], W1[k * F1 + c], acc);
        g_h[idx] = acc;
    }
    // preload W2 to smem (no dependency on phase 1 results)
    for (int i = tid; i < (F1 * F2) / 4; i += TT)
        ((float4*)sW2)[i] = ((const float4*)W2)[i];

    grid_bar(1 * TB);

    // ---- Phase 2: BN1 stats, block b owns column b (TB == F1) ----
    {
        int c = b;
        float v0 = g_h[tid * F1 + c];
        float v1 = g_h[(tid + 256) * F1 + c];
        sred[tid]      = v0 + v1;
        sred[TT + tid] = v0 * v0 + v1 * v1;
        __syncthreads();
        #pragma unroll
        for (int st = 128; st > 0; st >>= 1) {
            if (tid < st) {
                sred[tid]      += sred[tid + st];
                sred[TT + tid] += sred[TT + tid + st];
            }
            __syncthreads();
        }
        if (tid == 0) {
            float mu  = sred[0]  * (1.0f / (float)NB);
            float var = sred[TT] * (1.0f / (float)NB) - mu * mu;
            float sc  = g1[c] * rsqrtf(var + BN_EPS);
            g_s1[c] = sc;
            g_o1[c] = be1[c] - mu * sc;
        }
    }
    grid_bar(2 * TB);

    // stage BN1 affine params in smem
    if (tid < F1) { ss1[tid] = g_s1[tid]; so1[tid] = g_o1[tid]; }
    __syncthreads();

    // ---- Phase 3: out_pre = relu(BN1(h)) @ W2 + b2 (4 cols / thread, f4) ----
    {
        int base = gt * 4;                 // 0..65532
        int r = base >> 7;
        int c = base & (F2 - 1);
        const float4* bb = (const float4*)&b2[c];
        float4 acc = *bb;
        const float* hrow = &g_h[r * F1];
        #pragma unroll
        for (int k = 0; k < F1; k++) {
            float a = fmaxf(fmaf(hrow[k], ss1[k], so1[k]), 0.f);
            float4 w = ((const float4*)sW2)[(k * F2 + c) >> 2];
            acc.x = fmaf(a, w.x, acc.x);
            acc.y = fmaf(a, w.y, acc.y);
            acc.z = fmaf(a, w.z, acc.z);
            acc.w = fmaf(a, w.w, acc.w);
        }
        ((float4*)out)[gt] = acc;
    }
    grid_bar(3 * TB);

    // ---- Phase 4: BN2 stats, block b owns columns 2b, 2b+1 ----
    {
        int c  = b * 2 + (tid >> 7);
        int rt = tid & 127;
        float s = 0.f, q = 0.f;
        #pragma unroll
        for (int i = 0; i < 4; i++) {
            float v = out[(rt + i * 128) * F2 + c];
            s += v;
            q += v * v;
        }
        sred[tid]      = s;
        sred[TT + tid] = q;
        __syncthreads();
        #pragma unroll
        for (int st = 64; st > 0; st >>= 1) {
            if (rt < st) {
                sred[tid]      += sred[tid + st];
                sred[TT + tid] += sred[TT + tid + st];
            }
            __syncthreads();
        }
        if (rt == 0) {
            float mu  = sred[tid]      * (1.0f / (float)NB);
            float var = sred[TT + tid] * (1.0f / (float)NB) - mu * mu;
            float sc  = g2[c] * rsqrtf(var + BN_EPS);
            g_s2[c] = sc;
            g_o2[c] = be2[c] - mu * sc;
        }
    }
    grid_bar(4 * TB);

    // ---- Phase 5: apply BN2 in place (float4) ----
    {
        int base = gt * 4;
        int c = base & (F2 - 1);
        float4 v  = ((float4*)out)[gt];
        float4 sc = *(const float4*)&g_s2[c];
        float4 of = *(const float4*)&g_o2[c];
        v.x = fmaf(v.x, sc.x, of.x);
        v.y = fmaf(v.y, sc.y, of.y);
        v.z = fmaf(v.z, sc.z, of.z);
        v.w = fmaf(v.w, sc.w, of.w);
        ((float4*)out)[gt] = v;
    }
}

// ---------------------------------------------------------------------------
extern "C" void kernel_launch(void* const* d_in, const int* in_sizes, int n_in,
                              void* d_out, int out_size) {
    const float* x     = (const float*)d_in[0];
    const int*   len   = (const int*)  d_in[1];
    const float* W1    = (const float*)d_in[2];
    const float* b1    = (const float*)d_in[3];
    const float* g1    = (const float*)d_in[4];
    const float* beta1 = (const float*)d_in[5];
    const float* W2    = (const float*)d_in[6];
    const float* b2    = (const float*)d_in[7];
    const float* g2    = (const float*)d_in[8];
    const float* beta2 = (const float*)d_in[9];
    float* out = (float*)d_out;

    k_scan<<<1, NB>>>(len);
    k_segmean<<<NB, 256>>>((const float4*)x);
    k_tail<<<TB, TT>>>(W1, b1, g1, beta1, W2, b2, g2, beta2, out);
}